// round 1
// baseline (speedup 1.0000x reference)
#include <cuda_runtime.h>
#include <cuda_bf16.h>
#include <cstddef>

// Problem constants
#define PB   4
#define PN   2048
#define PDIM 1024
#define PH   16
#define PHD  64
#define PSCALE 0.125f           // HEAD_DIM^-0.5 = 64^-0.5

// Scratch (allocation-free rule: __device__ globals)
__device__ float g_qkv[(size_t)PB * PN * 3 * PDIM];   // [B, N, 3*DIM]  ~100 MB
__device__ float g_attn[(size_t)PB * PN * PDIM];      // [B, N, DIM]    ~33 MB

// ---------------------------------------------------------------------------
// Classic SGEMM: C[M, Nc] = A[M, K] @ B[K, Nc] (+ bias), fp32
// BM=BN=128, BK=8, 256 threads, 8x8 register tile per thread.
// ---------------------------------------------------------------------------
__global__ __launch_bounds__(256, 2)
void sgemm_kernel(const float* __restrict__ A, const float* __restrict__ B,
                  float* __restrict__ C, int M, int Ncols, int K,
                  const float* __restrict__ bias)
{
    const int BM = 128, BN = 128, BK = 8;
    __shared__ __align__(16) float As[BK][BM];
    __shared__ __align__(16) float Bs[BK][BN];

    const int tid = threadIdx.x;
    const int tx  = tid & 15;       // 0..15 -> 8 cols each
    const int ty  = tid >> 4;       // 0..15 -> 8 rows each
    const int bx  = blockIdx.x;     // N tile
    const int by  = blockIdx.y;     // M tile

    float acc[8][8];
#pragma unroll
    for (int i = 0; i < 8; i++)
#pragma unroll
        for (int j = 0; j < 8; j++) acc[i][j] = 0.0f;

    const float* Ab = A + (size_t)(by * BM) * K;
    const float* Bb = B + (size_t)(bx * BN);

    // A tile load mapping: 128 rows x 8 cols = 1024 floats -> 256 float4 along K
    const int aRow = tid >> 1;          // 0..127
    const int aCol = (tid & 1) * 4;     // 0 or 4
    // B tile load mapping: 8 rows x 128 cols = 1024 floats -> 256 float4 along N
    const int bRow = tid >> 5;          // 0..7
    const int bCol = (tid & 31) * 4;    // 0..124

    for (int k0 = 0; k0 < K; k0 += BK) {
        float4 a4 = *(const float4*)(Ab + (size_t)aRow * K + k0 + aCol);
        As[aCol + 0][aRow] = a4.x;
        As[aCol + 1][aRow] = a4.y;
        As[aCol + 2][aRow] = a4.z;
        As[aCol + 3][aRow] = a4.w;
        float4 b4 = *(const float4*)(Bb + (size_t)(k0 + bRow) * Ncols + bCol);
        *(float4*)&Bs[bRow][bCol] = b4;
        __syncthreads();

#pragma unroll
        for (int k = 0; k < BK; k++) {
            float ar[8], br[8];
            *(float4*)(ar)     = *(const float4*)&As[k][ty * 8];
            *(float4*)(ar + 4) = *(const float4*)&As[k][ty * 8 + 4];
            *(float4*)(br)     = *(const float4*)&Bs[k][tx * 8];
            *(float4*)(br + 4) = *(const float4*)&Bs[k][tx * 8 + 4];
#pragma unroll
            for (int i = 0; i < 8; i++)
#pragma unroll
                for (int j = 0; j < 8; j++)
                    acc[i][j] = fmaf(ar[i], br[j], acc[i][j]);
        }
        __syncthreads();
    }

    // Write out (with optional bias)
#pragma unroll
    for (int i = 0; i < 8; i++) {
        const size_t row = (size_t)(by * BM + ty * 8 + i);
        float* crow = C + row * Ncols + bx * BN + tx * 8;
#pragma unroll
        for (int j = 0; j < 8; j += 4) {
            float4 v;
            v.x = acc[i][j + 0];
            v.y = acc[i][j + 1];
            v.z = acc[i][j + 2];
            v.w = acc[i][j + 3];
            if (bias) {
                const float* bp = bias + bx * BN + tx * 8 + j;
                v.x += bp[0]; v.y += bp[1]; v.z += bp[2]; v.w += bp[3];
            }
            *(float4*)(crow + j) = v;
        }
    }
}

// ---------------------------------------------------------------------------
// Flash-attention style kernel (fp32, online softmax).
// Block handles BQ=64 queries for one (b, h). Streams over 64 key tiles of 32.
// 256 threads. Static SMEM ~42 KB (< 48 KB, no dynamic-smem attribute needed).
// ---------------------------------------------------------------------------
__global__ __launch_bounds__(256, 2)
void attn_kernel(const float* __restrict__ qkv, float* __restrict__ outp)
{
    __shared__ __align__(16) float Qs[64][64];   // scaled Q, [row][d]
    __shared__ float            Ks[32][65];      // [key][d], padded (conflict-free S reads)
    __shared__ __align__(16) float Vs[32][64];   // [key][d]
    __shared__ float            Ps[64][33];      // S then P, padded (conflict-free row scans)
    __shared__ float row_m[64], row_l[64], row_corr[64];

    const int tid = threadIdx.x;
    const int qt  = blockIdx.x;    // 0..31
    const int h   = blockIdx.y;    // 0..15
    const int b   = blockIdx.z;    // 0..3

    const size_t rstride = 3 * PDIM;
    const float* qb = qkv + ((size_t)(b * PN) + qt * 64) * rstride + h * PHD;

    // Load Q tile (scaled): 64x64 floats = 1024 float4
#pragma unroll
    for (int i = 0; i < 4; i++) {
        int e = tid + i * 256;            // float4 index
        int r = e >> 4;
        int d = (e & 15) * 4;
        float4 v = *(const float4*)(qb + (size_t)r * rstride + d);
        v.x *= PSCALE; v.y *= PSCALE; v.z *= PSCALE; v.w *= PSCALE;
        *(float4*)&Qs[r][d] = v;
    }
    if (tid < 64) { row_m[tid] = -1e30f; row_l[tid] = 0.0f; }

    float o[4][4];
#pragma unroll
    for (int i = 0; i < 4; i++)
#pragma unroll
        for (int j = 0; j < 4; j++) o[i][j] = 0.0f;

    const int tx = tid & 15;   // PV: d0 = tx*4
    const int ty = tid >> 4;   // PV: r0 = ty*4
    const int sx = tid & 7;    // S:  c0 = sx*4
    const int sy = tid >> 3;   // S:  r0 = sy*2
    __syncthreads();

    for (int j0 = 0; j0 < PN; j0 += 32) {
        const float* kb = qkv + ((size_t)(b * PN) + j0) * rstride + PDIM + h * PHD;
        const float* vb = kb + PDIM;
        // Load K (scalar store: padded rows) and V (vector store) tiles: 32x64 each
#pragma unroll
        for (int i = 0; i < 2; i++) {
            int e = tid + i * 256;        // 0..511 float4 ids (32*64/4)
            int r = e >> 4;
            int d = (e & 15) * 4;
            float4 k4 = *(const float4*)(kb + (size_t)r * rstride + d);
            Ks[r][d + 0] = k4.x; Ks[r][d + 1] = k4.y;
            Ks[r][d + 2] = k4.z; Ks[r][d + 3] = k4.w;
            float4 v4 = *(const float4*)(vb + (size_t)r * rstride + d);
            *(float4*)&Vs[r][d] = v4;
        }
        __syncthreads();

        // S = Qs @ Ks^T : [64 x 32], micro-tile 2x4
        {
            const int r0 = sy * 2, c0 = sx * 4;
            float s[2][4];
#pragma unroll
            for (int i = 0; i < 2; i++)
#pragma unroll
                for (int jj = 0; jj < 4; jj++) s[i][jj] = 0.0f;
#pragma unroll 8
            for (int k = 0; k < 64; k++) {
                float q0 = Qs[r0][k];
                float q1 = Qs[r0 + 1][k];
#pragma unroll
                for (int jj = 0; jj < 4; jj++) {
                    float kv = Ks[c0 + jj][k];
                    s[0][jj] = fmaf(q0, kv, s[0][jj]);
                    s[1][jj] = fmaf(q1, kv, s[1][jj]);
                }
            }
#pragma unroll
            for (int i = 0; i < 2; i++)
#pragma unroll
                for (int jj = 0; jj < 4; jj++)
                    Ps[r0 + i][c0 + jj] = s[i][jj];
        }
        __syncthreads();

        // Online softmax update: one thread per query row
        if (tid < 64) {
            const int r = tid;
            float mx = row_m[r];
            float tm = -1e30f;
#pragma unroll
            for (int c = 0; c < 32; c++) tm = fmaxf(tm, Ps[r][c]);
            float nm   = fmaxf(mx, tm);
            float corr = __expf(mx - nm);
            float sum  = 0.0f;
#pragma unroll
            for (int c = 0; c < 32; c++) {
                float p = __expf(Ps[r][c] - nm);
                Ps[r][c] = p;
                sum += p;
            }
            row_l[r]    = row_l[r] * corr + sum;
            row_m[r]    = nm;
            row_corr[r] = corr;
        }
        __syncthreads();

        // O = O*corr + P @ V : [64 x 64], micro-tile 4x4
        {
            const int r0 = ty * 4, d0 = tx * 4;
            float c0f = row_corr[r0 + 0], c1f = row_corr[r0 + 1];
            float c2f = row_corr[r0 + 2], c3f = row_corr[r0 + 3];
#pragma unroll
            for (int jj = 0; jj < 4; jj++) {
                o[0][jj] *= c0f; o[1][jj] *= c1f;
                o[2][jj] *= c2f; o[3][jj] *= c3f;
            }
#pragma unroll 8
            for (int c = 0; c < 32; c++) {
                float4 vv = *(const float4*)&Vs[c][d0];
                float p0 = Ps[r0 + 0][c], p1 = Ps[r0 + 1][c];
                float p2 = Ps[r0 + 2][c], p3 = Ps[r0 + 3][c];
                o[0][0] = fmaf(p0, vv.x, o[0][0]); o[0][1] = fmaf(p0, vv.y, o[0][1]);
                o[0][2] = fmaf(p0, vv.z, o[0][2]); o[0][3] = fmaf(p0, vv.w, o[0][3]);
                o[1][0] = fmaf(p1, vv.x, o[1][0]); o[1][1] = fmaf(p1, vv.y, o[1][1]);
                o[1][2] = fmaf(p1, vv.z, o[1][2]); o[1][3] = fmaf(p1, vv.w, o[1][3]);
                o[2][0] = fmaf(p2, vv.x, o[2][0]); o[2][1] = fmaf(p2, vv.y, o[2][1]);
                o[2][2] = fmaf(p2, vv.z, o[2][2]); o[2][3] = fmaf(p2, vv.w, o[2][3]);
                o[3][0] = fmaf(p3, vv.x, o[3][0]); o[3][1] = fmaf(p3, vv.y, o[3][1]);
                o[3][2] = fmaf(p3, vv.z, o[3][2]); o[3][3] = fmaf(p3, vv.w, o[3][3]);
            }
        }
        __syncthreads();
    }

    // Normalize and write: out[b, qt*64 + r, h*64 + d]
    {
        const int r0 = ty * 4, d0 = tx * 4;
        float* ob = outp + ((size_t)(b * PN) + qt * 64) * PDIM + h * PHD;
#pragma unroll
        for (int i = 0; i < 4; i++) {
            float inv = 1.0f / row_l[r0 + i];
            float4 v;
            v.x = o[i][0] * inv; v.y = o[i][1] * inv;
            v.z = o[i][2] * inv; v.w = o[i][3] * inv;
            *(float4*)(ob + (size_t)(r0 + i) * PDIM + d0) = v;
        }
    }
}

// ---------------------------------------------------------------------------
// Launch: x @ w_qkv -> g_qkv ; attention -> g_attn ; g_attn @ w_proj + b
// ---------------------------------------------------------------------------
extern "C" void kernel_launch(void* const* d_in, const int* in_sizes, int n_in,
                              void* d_out, int out_size)
{
    const float* x      = (const float*)d_in[0];   // [4, 2048, 1024]
    const float* w_qkv  = (const float*)d_in[1];   // [1024, 3072]
    const float* w_proj = (const float*)d_in[2];   // [1024, 1024]
    const float* b_proj = (const float*)d_in[3];   // [1024]
    float* out = (float*)d_out;                    // [4, 2048, 1024]

    float* qkv = nullptr;
    float* att = nullptr;
    cudaGetSymbolAddress((void**)&qkv, g_qkv);
    cudaGetSymbolAddress((void**)&att, g_attn);

    const int M = PB * PN;          // 8192

    // 1) qkv = x @ w_qkv  : [8192,1024] @ [1024,3072]
    {
        dim3 grid(3 * PDIM / 128, M / 128);
        sgemm_kernel<<<grid, 256>>>(x, w_qkv, qkv, M, 3 * PDIM, PDIM, nullptr);
    }

    // 2) attention per (b, h, qtile)
    {
        dim3 grid(PN / 64, PH, PB);
        attn_kernel<<<grid, 256>>>(qkv, att);
    }

    // 3) out = att @ w_proj + b_proj : [8192,1024] @ [1024,1024]
    {
        dim3 grid(PDIM / 128, M / 128);
        sgemm_kernel<<<grid, 256>>>(att, w_proj, out, M, PDIM, PDIM, b_proj);
    }
}